// round 5
// baseline (speedup 1.0000x reference)
#include <cuda_runtime.h>
#include <math.h>

#define FULLMASK 0xffffffffu
#define NS   25
#define NF   216
#define TLEN 2048

// ---------------- constant tables ----------------
__constant__ __align__(16) int c_srcTab[32 * 4] = {
    0,0,0,0,     0,1,1,1,     1,2,2,2,     2,3,3,3,
    3,16,4,4,    4,5,5,5,     5,6,6,6,     6,19,3,7,
    7,8,8,8,     8,9,9,9,     9,22,3,6,    10,11,11,11,
    11,12,12,12, 12,13,13,13, 3,16,14,14,  14,15,15,15,
    15,16,16,16, 6,19,17,17,  17,18,18,18, 18,19,19,19,
    9,22,20,20,  20,21,21,21, 21,22,22,22, 13,23,23,23,
    23,24,24,24, 25,25,25,25, 26,26,26,26, 27,27,27,27,
    28,28,28,28, 29,29,29,29, 30,30,30,30, 31,31,31,31
};
__constant__ int c_deg[32] = {1,1,1,1,2,1,1,3,1,1,4,1,1,2,2,1,1,2,1,1,2,1,1,2,2,0,0,0,0,0,0,0};

__constant__ int c_pred[25][4] = {
    {0,0,0,0},{0,0,0,0},{1,0,0,0},{2,0,0,0},{3,16,0,0},{4,0,0,0},{5,0,0,0},
    {6,19,3,0},{7,0,0,0},{8,0,0,0},{9,22,3,6},{10,0,0,0},{11,0,0,0},{12,13,0,0},
    {3,16,0,0},{14,0,0,0},{15,0,0,0},{6,19,0,0},{17,0,0,0},{18,0,0,0},
    {9,22,0,0},{20,0,0,0},{21,0,0,0},{13,23,0,0},{23,24,0,0}
};
__constant__ int c_pcnt[25] = {1,1,1,1,2,1,1,3,1,1,4,1,1,2,2,1,1,2,1,1,2,1,1,2,2};

__constant__ int c_adds[29][7] = {
    { 0, 10,10,10, 0,1,    0},
    { 1, 10,10, 0, 0,1,   84},
    { 2, 10, 0, 3, 0,1,  105},
    { 3,  0, 3, 2, 0,0,    0},
    { 4,  3, 2,10, 0,1,  111},
    { 5,  2,10,10, 0,1,  123},
    { 6, 10,10,10, 0,1,  159},
    { 7, 10,10,10, 0,1,  243},
    { 8, 10,10,10, 0,1,  327},
    { 9, 10,10,10, 0,1,  411},
    {10, 10,10, 3, 2,1,  495},
    {11, 10, 3, 0, 2,1,  511},
    {11, 10, 3, 2, 2,1,  515},
    {12,  3, 0, 0, 2,0,    0},
    {12,  3, 0, 2, 2,0,    0},
    {12,  3, 2, 0, 2,0,    0},
    {13, 10,10,10, 2,1,  519},
    {14, 10,10,10, 0,1,  583},
    {15, 10,10,10, 0,1,  667},
    {16, 10,10,10, 0,1,  751},
    {17, 10,10,10, 0,1,  835},
    {18, 10,10,10, 0,1,  919},
    {19, 10,10,10, 0,1, 1003},
    {20, 10,10,10, 0,1, 1087},
    {21, 10,10,10, 0,1, 1171},
    {22, 10,10,10, 0,1, 1255},
    {23, 10,10, 5, 2,1, 1339},
    {23, 10, 5, 5, 2,1, 1355},
    {24,  5, 5, 5, 2,0,    0}
};

// ---------------- helpers ----------------
__device__ __forceinline__ int codeList(int ch, int* o) {
    if (ch == 10) { o[0]=0; o[1]=1; o[2]=2; o[3]=3; return 4; }
    o[0] = ch; return 1;
}

__device__ void addB(float* shB, const float* w,
                     int state, int e0, int e1, int e2,
                     int xp, int trainable, int k)
{
    int a0[6], a1[6], a2[6];
    int n0 = codeList(e0, a0);
    int n1 = codeList(e1, a1);
    int n2 = codeList(e2, a2);
    if (xp == 0) { a0[n0++] = 4; a1[n1++] = 4; }
    int t = 0;
    for (int i0 = 0; i0 < n0; i0++) { int c0 = a0[i0];
        for (int i1 = 0; i1 < n1; i1++) { int c1 = a1[i1];
            if (c0 != 4 && c1 == 4) continue;
            for (int i2 = 0; i2 < n2; i2++) { int c2 = a2[i2];
                shB[((c0*36 + c1*6 + c2) << 5) + state] = trainable ? w[k + t] : 1.0f;
                t++;
            }
        }
    }
}

// ---------------- fused kernel ----------------
__global__ __launch_bounds__(128)
void hmm_fused(const float* __restrict__ tw,
               const float* __restrict__ ew,
               const float* __restrict__ iw,
               const int* __restrict__ tokens,
               float* __restrict__ out, int rows)
{
    __shared__ float shB[NF * 32];   // B^T padded: [flat][state(32)]
    __shared__ float sA[25 * 25];
    __shared__ float sI[32];
    __shared__ float sRed[4 * 32];
    const int tid = threadIdx.x;

    // ---- init ----
    for (int i = tid; i < NF*32; i += 128) shB[i] = ((i & 31) < 25) ? -1e30f : 0.0f;
    for (int i = tid; i < 25*25;  i += 128) sA[i] = -1e30f;
    __syncthreads();

    // ---- B logits (29 disjoint adds) ----
    if (tid < 29) {
        const int* d = c_adds[tid];
        addB(shB, ew, d[0], d[1], d[2], d[3], d[4], d[5], d[6]);
    }
    // ---- A logits ----
    if (tid == 32) {
        float w0=tw[0],w1=tw[1],w2=tw[2],w3=tw[3],w4=tw[4];
        float w5=tw[5],w6=tw[6],w7=tw[7],w8=tw[8],w9=tw[9];
        sA[0*25+0]=1.f-w0; sA[0*25+1]=w0;
        sA[1*25+2]=1.f;    sA[2*25+3]=1.f;
        sA[3*25+4]=w1;     sA[6*25+7]=w2;
        sA[4*25+5]=1.f;    sA[7*25+8]=1.f;
        sA[5*25+6]=1.f;    sA[8*25+9]=1.f;
        sA[3*25+14]=w3;    sA[6*25+17]=w4;   sA[9*25+20]=w5;
        sA[9*25+10]=1.f-w5;
        sA[14*25+15]=1.f;  sA[17*25+18]=1.f; sA[20*25+21]=1.f;
        sA[15*25+16]=1.f;  sA[18*25+19]=1.f; sA[21*25+22]=1.f;
        sA[16*25+4]=w6;    sA[19*25+7]=w7;   sA[22*25+10]=w8;
        sA[16*25+14]=1.f-w6; sA[19*25+17]=1.f-w7; sA[22*25+20]=1.f-w8;
        sA[3*25+7]=1.f - w9*w9;
        sA[3*25+10]=1.f - w9*w9*w9;
        sA[6*25+10]=1.f - w9*w9;
        sA[10*25+11]=1.f; sA[11*25+12]=1.f; sA[12*25+13]=1.f;
        sA[13*25+13]=1.f; sA[13*25+23]=1.f;
        sA[23*25+23]=1.f; sA[23*25+24]=1.f; sA[24*25+24]=1.f;
    }
    // ---- I softmax (9 entries) ----
    if (tid == 64) {
        float mx = -1e30f;
        for (int i = 0; i < 9; i++) mx = fmaxf(mx, iw[i]);
        float v[9], sum = 0.f;
        for (int i = 0; i < 9; i++) { v[i] = expf(iw[i]-mx); sum += v[i]; }
        for (int i = 0; i < 9; i++) sI[i] = v[i] / sum;
        for (int i = 9; i < 32; i++) sI[i] = 0.f;
    }
    __syncthreads();

    // ---- A row softmax (thread per row) ----
    if (tid < 25) {
        float mx = -1e30f;
        for (int j = 0; j < 25; j++) mx = fmaxf(mx, sA[tid*25+j]);
        float s = 0.f;
        for (int j = 0; j < 25; j++) { float v = expf(sA[tid*25+j]-mx); sA[tid*25+j]=v; s+=v; }
        float inv = 1.f / s;
        for (int j = 0; j < 25; j++) sA[tid*25+j] *= inv;
    }
    // ---- B column softmax, 4-way parallel per state (conflict-free) ----
    {
        const int s  = tid & 31;
        const int ch = tid >> 5;
        const int f0 = ch * 54, f1 = f0 + 54;
        float mx = -1e30f;
        for (int f = f0; f < f1; f++) mx = fmaxf(mx, shB[(f<<5)+s]);
        sRed[ch*32 + s] = mx;
        __syncthreads();
        mx = fmaxf(fmaxf(sRed[s], sRed[32+s]), fmaxf(sRed[64+s], sRed[96+s]));
        float sum = 0.f;
        for (int f = f0; f < f1; f++) {
            float v = __expf(shB[(f<<5)+s] - mx);
            shB[(f<<5)+s] = v; sum += v;
        }
        __syncthreads();
        sRed[ch*32 + s] = sum;
        __syncthreads();
        float tot = (sRed[s] + sRed[32+s]) + (sRed[64+s] + sRed[96+s]);
        float inv = 1.f / tot;
        for (int f = f0; f < f1; f++) shB[(f<<5)+s] *= inv;
    }
    __syncthreads();

    // ---- per-lane constants ----
    const int lane = tid & 31;

    // 2-step path table: up to 4 paths (i -> k -> j), j = lane
    int   ps[4] = {0,0,0,0};
    int   pk[4]; pk[0]=0; pk[1]=0; pk[2]=0; pk[3]=0;
    float pc[4] = {0.f,0.f,0.f,0.f};
    if (lane < 25) {
        int cnt = 0;
        for (int ki = 0; ki < c_pcnt[lane]; ki++) {
            int k = c_pred[lane][ki];
            float akj = sA[k*25 + lane];
            for (int ii = 0; ii < c_pcnt[k]; ii++) {
                int i = c_pred[k][ii];
                ps[cnt] = i; pk[cnt] = k;
                pc[cnt] = sA[i*25 + k] * akj;
                cnt++;
            }
        }
    }
    const int   S0 = ps[0], S1 = ps[1], S2 = ps[2], S3 = ps[3];
    const int   K0 = pk[0], K1 = pk[1], K2 = pk[2], K3 = pk[3];
    const float C0 = pc[0], C1 = pc[1], C2 = pc[2], C3 = pc[3];

    // 1-step table (t=1 and tail)
    const int u0 = c_srcTab[lane*4+0], u1 = c_srcTab[lane*4+1];
    const int u2 = c_srcTab[lane*4+2], u3 = c_srcTab[lane*4+3];
    const int dg = c_deg[lane];
    float v0 = (lane < 25 && dg > 0) ? sA[u0*25 + lane] : 0.f;
    float v1 = (lane < 25 && dg > 1) ? sA[u1*25 + lane] : 0.f;
    float v2 = (lane < 25 && dg > 2) ? sA[u2*25 + lane] : 0.f;
    float v3 = (lane < 25 && dg > 3) ? sA[u3*25 + lane] : 0.f;

    const int row = blockIdx.x * 4 + (tid >> 5);
    if (row >= rows) return;
    const int* tok = tokens + (size_t)row * TLEN;

    // ---- t = 0 ----
    const int tok0 = tok[0], tok1 = tok[1];
    float a = sI[lane] * shB[((168 + tok0) << 5) + lane];

    // ---- t = 1: single 1-step ----
    {
        float e = shB[((144 + tok0*6 + tok1) << 5) + lane];
        float x0 = __shfl_sync(FULLMASK, a, u0);
        float x1 = __shfl_sync(FULLMASK, a, u1);
        float x2 = __shfl_sync(FULLMASK, a, u2);
        float x3 = __shfl_sync(FULLMASK, a, u3);
        a = (fmaf(x0, v0, x1*v1) + fmaf(x2, v2, x3*v3)) * e;
    }
    int expsum = 0;

    // ================== software-pipelined main loop ==================
    // 127 tiles of 16 steps: t = 2 .. 2033. Wc = coefficients for current
    // tile (precomputed); Wn built inside the loop for the NEXT tile so the
    // independent staging instructions fill the alpha-chain stall cycles.
    float Wc[32];

    // -- prologue: build Wc for tile0 (t0 = 2) --
    int tm2 = 0, tm1 = 0, tc = 0;
    if (lane < 16) { int t = 2 + lane; tm2 = tok[t-2]; tm1 = tok[t-1]; tc = tok[t]; }
    {
        int flatv = tm2*36 + tm1*6 + tc;
        float E[16];
        #pragma unroll
        for (int s = 0; s < 16; s++) {
            int f = __shfl_sync(FULLMASK, flatv, s);
            E[s] = shB[(f << 5) + lane];
        }
        #pragma unroll
        for (int i = 0; i < 8; i++) {
            float e1 = E[2*i+1];
            float p0 = C0*e1, p1 = C1*e1, p2 = C2*e1, p3 = C3*e1;
            Wc[4*i+0] = p0 * __shfl_sync(FULLMASK, E[2*i], K0);
            Wc[4*i+1] = p1 * __shfl_sync(FULLMASK, E[2*i], K1);
            Wc[4*i+2] = p2 * __shfl_sync(FULLMASK, E[2*i], K2);
            Wc[4*i+3] = p3 * __shfl_sync(FULLMASK, E[2*i], K3);
        }
    }
    // tokens for tile1 (t0 = 18)
    if (lane < 16) { int t = 18 + lane; tm2 = tok[t-2]; tm1 = tok[t-1]; tc = tok[t]; }

    for (int t0 = 2; t0 <= 2018; t0 += 16) {
        // ---- build Wn for next tile (stale/garbage on the last iter; discarded) ----
        float Wn[32];
        {
            int flatv = tm2*36 + tm1*6 + tc;
            float E[16];
            #pragma unroll
            for (int s = 0; s < 16; s++) {
                int f = __shfl_sync(FULLMASK, flatv, s);
                E[s] = shB[(f << 5) + lane];
            }
            #pragma unroll
            for (int i = 0; i < 8; i++) {
                float e1 = E[2*i+1];
                float p0 = C0*e1, p1 = C1*e1, p2 = C2*e1, p3 = C3*e1;
                Wn[4*i+0] = p0 * __shfl_sync(FULLMASK, E[2*i], K0);
                Wn[4*i+1] = p1 * __shfl_sync(FULLMASK, E[2*i], K1);
                Wn[4*i+2] = p2 * __shfl_sync(FULLMASK, E[2*i], K2);
                Wn[4*i+3] = p3 * __shfl_sync(FULLMASK, E[2*i], K3);
            }
        }
        // ---- predicated prefetch of tile(t0+32) tokens ----
        {
            int t = t0 + 32 + lane;
            if (t0 + 32 <= 2018 && lane < 16) {
                tm2 = tok[t-2]; tm1 = tok[t-1]; tc = tok[t];
            }
        }
        // ---- alpha loop: 8 pairs, only 4 shfl + fma tree on the chain ----
        float sc = 1.f; int pend = 0;
        #pragma unroll
        for (int i = 0; i < 8; i++) {
            float x0 = __shfl_sync(FULLMASK, a, S0);
            float x1 = __shfl_sync(FULLMASK, a, S1);
            float x2 = __shfl_sync(FULLMASK, a, S2);
            float x3 = __shfl_sync(FULLMASK, a, S3);
            a = fmaf(x1, Wc[4*i+1], x0*Wc[4*i+0]) + fmaf(x3, Wc[4*i+3], x2*Wc[4*i+2]);

            if ((i & 3) == 2) {
                int m = __reduce_max_sync(FULLMASK, (__float_as_int(a) >> 23) & 255);
                sc = __int_as_float((254 - m) << 23);
                pend = m - 127;
            }
            if ((i & 3) == 3) {
                a *= sc;
                expsum += pend;
            }
        }
        // ---- rotate ----
        #pragma unroll
        for (int k = 0; k < 32; k++) Wc[k] = Wn[k];
    }

    // ---- tail: t = 2034 .. 2047 (14 single steps) ----
    for (int t = 2034; t < TLEN; t++) {
        int f = tok[t-2]*36 + tok[t-1]*6 + tok[t];
        float e = shB[(f << 5) + lane];
        float x0 = __shfl_sync(FULLMASK, a, u0);
        float x1 = __shfl_sync(FULLMASK, a, u1);
        float x2 = __shfl_sync(FULLMASK, a, u2);
        float x3 = __shfl_sync(FULLMASK, a, u3);
        a = (fmaf(x0, v0, x1*v1) + fmaf(x2, v2, x3*v3)) * e;
        if (t == 2041) {
            int m = __reduce_max_sync(FULLMASK, (__float_as_int(a) >> 23) & 255);
            a *= __int_as_float((254 - m) << 23);
            expsum += m - 127;
        }
    }

    // ---- final ----
    float s = a;
    #pragma unroll
    for (int o = 16; o; o >>= 1) s += __shfl_xor_sync(FULLMASK, s, o);
    if (lane == 0)
        out[row] = logf(s) + 0.6931471805599453f * (float)expsum;
}

// ---------------- entry point ----------------
extern "C" void kernel_launch(void* const* d_in, const int* in_sizes, int n_in,
                              void* d_out, int out_size)
{
    const float* tw     = (const float*)d_in[0];
    const float* ew     = (const float*)d_in[1];
    const float* iw     = (const float*)d_in[2];
    const int*   tokens = (const int*)  d_in[3];
    float*       out    = (float*)d_out;

    int rows = in_sizes[3] / TLEN;

    hmm_fused<<<(rows + 3) / 4, 128>>>(tw, ew, iw, tokens, out, rows);
}

// round 6
// speedup vs baseline: 1.1382x; 1.1382x over previous
#include <cuda_runtime.h>
#include <math.h>

#define FULLMASK 0xffffffffu
#define NS   25
#define NF   216
#define TLEN 2048

// ---------------- constant tables ----------------
__constant__ __align__(16) int c_srcTab[32 * 4] = {
    0,0,0,0,     0,1,1,1,     1,2,2,2,     2,3,3,3,
    3,16,4,4,    4,5,5,5,     5,6,6,6,     6,19,3,7,
    7,8,8,8,     8,9,9,9,     9,22,3,6,    10,11,11,11,
    11,12,12,12, 12,13,13,13, 3,16,14,14,  14,15,15,15,
    15,16,16,16, 6,19,17,17,  17,18,18,18, 18,19,19,19,
    9,22,20,20,  20,21,21,21, 21,22,22,22, 13,23,23,23,
    23,24,24,24, 25,25,25,25, 26,26,26,26, 27,27,27,27,
    28,28,28,28, 29,29,29,29, 30,30,30,30, 31,31,31,31
};
__constant__ int c_deg[32] = {1,1,1,1,2,1,1,3,1,1,4,1,1,2,2,1,1,2,1,1,2,1,1,2,2,0,0,0,0,0,0,0};

__constant__ int c_pred[25][4] = {
    {0,0,0,0},{0,0,0,0},{1,0,0,0},{2,0,0,0},{3,16,0,0},{4,0,0,0},{5,0,0,0},
    {6,19,3,0},{7,0,0,0},{8,0,0,0},{9,22,3,6},{10,0,0,0},{11,0,0,0},{12,13,0,0},
    {3,16,0,0},{14,0,0,0},{15,0,0,0},{6,19,0,0},{17,0,0,0},{18,0,0,0},
    {9,22,0,0},{20,0,0,0},{21,0,0,0},{13,23,0,0},{23,24,0,0}
};
__constant__ int c_pcnt[25] = {1,1,1,1,2,1,1,3,1,1,4,1,1,2,2,1,1,2,1,1,2,1,1,2,2};

__constant__ int c_adds[29][7] = {
    { 0, 10,10,10, 0,1,    0},
    { 1, 10,10, 0, 0,1,   84},
    { 2, 10, 0, 3, 0,1,  105},
    { 3,  0, 3, 2, 0,0,    0},
    { 4,  3, 2,10, 0,1,  111},
    { 5,  2,10,10, 0,1,  123},
    { 6, 10,10,10, 0,1,  159},
    { 7, 10,10,10, 0,1,  243},
    { 8, 10,10,10, 0,1,  327},
    { 9, 10,10,10, 0,1,  411},
    {10, 10,10, 3, 2,1,  495},
    {11, 10, 3, 0, 2,1,  511},
    {11, 10, 3, 2, 2,1,  515},
    {12,  3, 0, 0, 2,0,    0},
    {12,  3, 0, 2, 2,0,    0},
    {12,  3, 2, 0, 2,0,    0},
    {13, 10,10,10, 2,1,  519},
    {14, 10,10,10, 0,1,  583},
    {15, 10,10,10, 0,1,  667},
    {16, 10,10,10, 0,1,  751},
    {17, 10,10,10, 0,1,  835},
    {18, 10,10,10, 0,1,  919},
    {19, 10,10,10, 0,1, 1003},
    {20, 10,10,10, 0,1, 1087},
    {21, 10,10,10, 0,1, 1171},
    {22, 10,10,10, 0,1, 1255},
    {23, 10,10, 5, 2,1, 1339},
    {23, 10, 5, 5, 2,1, 1355},
    {24,  5, 5, 5, 2,0,    0}
};

// ---------------- helpers ----------------
__device__ __forceinline__ int codeList(int ch, int* o) {
    if (ch == 10) { o[0]=0; o[1]=1; o[2]=2; o[3]=3; return 4; }
    o[0] = ch; return 1;
}

__device__ void addB(float* shB, const float* w,
                     int state, int e0, int e1, int e2,
                     int xp, int trainable, int k)
{
    int a0[6], a1[6], a2[6];
    int n0 = codeList(e0, a0);
    int n1 = codeList(e1, a1);
    int n2 = codeList(e2, a2);
    if (xp == 0) { a0[n0++] = 4; a1[n1++] = 4; }
    int t = 0;
    for (int i0 = 0; i0 < n0; i0++) { int c0 = a0[i0];
        for (int i1 = 0; i1 < n1; i1++) { int c1 = a1[i1];
            if (c0 != 4 && c1 == 4) continue;
            for (int i2 = 0; i2 < n2; i2++) { int c2 = a2[i2];
                shB[((c0*36 + c1*6 + c2) << 5) + state] = trainable ? w[k + t] : 1.0f;
                t++;
            }
        }
    }
}

// ---------------- fused kernel ----------------
__global__ __launch_bounds__(128)
void hmm_fused(const float* __restrict__ tw,
               const float* __restrict__ ew,
               const float* __restrict__ iw,
               const int* __restrict__ tokens,
               float* __restrict__ out, int rows)
{
    __shared__ float shB[NF * 32];     // B^T padded: [flat][state(32)]  27648 B
    __shared__ short sFlat[4 * TLEN];  // per-warp flat contexts         16384 B
    __shared__ float sA[25 * 25];
    __shared__ float sI[32];
    __shared__ float sRed[4 * 32];
    const int tid = threadIdx.x;

    // ---- init ----
    for (int i = tid; i < NF*32; i += 128) shB[i] = ((i & 31) < 25) ? -1e30f : 0.0f;
    for (int i = tid; i < 25*25;  i += 128) sA[i] = -1e30f;
    __syncthreads();

    // ---- B logits (29 disjoint adds) ----
    if (tid < 29) {
        const int* d = c_adds[tid];
        addB(shB, ew, d[0], d[1], d[2], d[3], d[4], d[5], d[6]);
    }
    // ---- A logits ----
    if (tid == 32) {
        float w0=tw[0],w1=tw[1],w2=tw[2],w3=tw[3],w4=tw[4];
        float w5=tw[5],w6=tw[6],w7=tw[7],w8=tw[8],w9=tw[9];
        sA[0*25+0]=1.f-w0; sA[0*25+1]=w0;
        sA[1*25+2]=1.f;    sA[2*25+3]=1.f;
        sA[3*25+4]=w1;     sA[6*25+7]=w2;
        sA[4*25+5]=1.f;    sA[7*25+8]=1.f;
        sA[5*25+6]=1.f;    sA[8*25+9]=1.f;
        sA[3*25+14]=w3;    sA[6*25+17]=w4;   sA[9*25+20]=w5;
        sA[9*25+10]=1.f-w5;
        sA[14*25+15]=1.f;  sA[17*25+18]=1.f; sA[20*25+21]=1.f;
        sA[15*25+16]=1.f;  sA[18*25+19]=1.f; sA[21*25+22]=1.f;
        sA[16*25+4]=w6;    sA[19*25+7]=w7;   sA[22*25+10]=w8;
        sA[16*25+14]=1.f-w6; sA[19*25+17]=1.f-w7; sA[22*25+20]=1.f-w8;
        sA[3*25+7]=1.f - w9*w9;
        sA[3*25+10]=1.f - w9*w9*w9;
        sA[6*25+10]=1.f - w9*w9;
        sA[10*25+11]=1.f; sA[11*25+12]=1.f; sA[12*25+13]=1.f;
        sA[13*25+13]=1.f; sA[13*25+23]=1.f;
        sA[23*25+23]=1.f; sA[23*25+24]=1.f; sA[24*25+24]=1.f;
    }
    // ---- I softmax (9 entries) ----
    if (tid == 64) {
        float mx = -1e30f;
        for (int i = 0; i < 9; i++) mx = fmaxf(mx, iw[i]);
        float v[9], sum = 0.f;
        for (int i = 0; i < 9; i++) { v[i] = expf(iw[i]-mx); sum += v[i]; }
        for (int i = 0; i < 9; i++) sI[i] = v[i] / sum;
        for (int i = 9; i < 32; i++) sI[i] = 0.f;
    }

    // ---- per-warp: precompute flat contexts for own row (overlaps with above) ----
    const int lane = tid & 31;
    const int wq   = tid >> 5;
    const int row  = blockIdx.x * 4 + wq;
    short* myFlat = sFlat + wq * TLEN;
    const int* tok = tokens + (size_t)row * TLEN;
    if (row < rows) {
        int c1 = 4, c2 = 4;   // pad tokens
        for (int t0 = 0; t0 < TLEN; t0 += 32) {
            int tcv = tok[t0 + lane];
            int t1v = __shfl_up_sync(FULLMASK, tcv, 1);
            int t2v = __shfl_up_sync(FULLMASK, tcv, 2);
            if (lane == 0) { t1v = c1; t2v = c2; }
            if (lane == 1) { t2v = c1; }
            myFlat[t0 + lane] = (short)(t2v*36 + t1v*6 + tcv);
            c2 = __shfl_sync(FULLMASK, tcv, 30);
            c1 = __shfl_sync(FULLMASK, tcv, 31);
        }
    }
    __syncthreads();

    // ---- A row softmax (thread per row) ----
    if (tid < 25) {
        float mx = -1e30f;
        for (int j = 0; j < 25; j++) mx = fmaxf(mx, sA[tid*25+j]);
        float s = 0.f;
        for (int j = 0; j < 25; j++) { float v = expf(sA[tid*25+j]-mx); sA[tid*25+j]=v; s+=v; }
        float inv = 1.f / s;
        for (int j = 0; j < 25; j++) sA[tid*25+j] *= inv;
    }
    // ---- B column softmax, 4-way parallel per state (conflict-free) ----
    {
        const int s  = tid & 31;
        const int ch = tid >> 5;
        const int f0 = ch * 54, f1 = f0 + 54;
        float mx = -1e30f;
        for (int f = f0; f < f1; f++) mx = fmaxf(mx, shB[(f<<5)+s]);
        sRed[ch*32 + s] = mx;
        __syncthreads();
        mx = fmaxf(fmaxf(sRed[s], sRed[32+s]), fmaxf(sRed[64+s], sRed[96+s]));
        float sum = 0.f;
        for (int f = f0; f < f1; f++) {
            float v = __expf(shB[(f<<5)+s] - mx);
            shB[(f<<5)+s] = v; sum += v;
        }
        __syncthreads();
        sRed[ch*32 + s] = sum;
        __syncthreads();
        float tot = (sRed[s] + sRed[32+s]) + (sRed[64+s] + sRed[96+s]);
        float inv = 1.f / tot;
        for (int f = f0; f < f1; f++) shB[(f<<5)+s] *= inv;
    }
    __syncthreads();

    // ---- per-lane constants ----
    // 2-step path table: up to 4 paths (i -> k -> j), j = lane
    int   ps[4] = {0,0,0,0};
    int   pk[4]; pk[0]=0; pk[1]=0; pk[2]=0; pk[3]=0;
    float pc[4] = {0.f,0.f,0.f,0.f};
    if (lane < 25) {
        int cnt = 0;
        for (int ki = 0; ki < c_pcnt[lane]; ki++) {
            int k = c_pred[lane][ki];
            float akj = sA[k*25 + lane];
            for (int ii = 0; ii < c_pcnt[k]; ii++) {
                int i = c_pred[k][ii];
                ps[cnt] = i; pk[cnt] = k;
                pc[cnt] = sA[i*25 + k] * akj;
                cnt++;
            }
        }
    }
    const int   S0 = ps[0], S1 = ps[1], S2 = ps[2], S3 = ps[3];
    const int   K0 = pk[0], K1 = pk[1], K2 = pk[2], K3 = pk[3];
    const float C0 = pc[0], C1 = pc[1], C2 = pc[2], C3 = pc[3];

    // 1-step table (t=1)
    const int u0 = c_srcTab[lane*4+0], u1 = c_srcTab[lane*4+1];
    const int u2 = c_srcTab[lane*4+2], u3 = c_srcTab[lane*4+3];
    const int dg = c_deg[lane];
    float v0 = (lane < 25 && dg > 0) ? sA[u0*25 + lane] : 0.f;
    float v1 = (lane < 25 && dg > 1) ? sA[u1*25 + lane] : 0.f;
    float v2 = (lane < 25 && dg > 2) ? sA[u2*25 + lane] : 0.f;
    float v3 = (lane < 25 && dg > 3) ? sA[u3*25 + lane] : 0.f;

    if (row >= rows) return;

    // ---- t = 0 ----
    float a = sI[lane] * shB[((int)myFlat[0] << 5) + lane];

    // ---- t = 1: single 1-step ----
    {
        float e = shB[((int)myFlat[1] << 5) + lane];
        float x0 = __shfl_sync(FULLMASK, a, u0);
        float x1 = __shfl_sync(FULLMASK, a, u1);
        float x2 = __shfl_sync(FULLMASK, a, u2);
        float x3 = __shfl_sync(FULLMASK, a, u3);
        a = (fmaf(x0, v0, x1*v1) + fmaf(x2, v2, x3*v3)) * e;
    }
    int expsum = 0;

    // ---- main loop: 1023 pairs (t = 2p, 2p+1), p = 1..1023 ----
    const short2* fp = (const short2*)myFlat;   // fp[p] = {flat[2p], flat[2p+1]}
    float sc = 1.f; int pend = 0;

    // MODE: 0 = plain, 1 = measure (REDUX off-chain), 2 = apply scale
#define PAIR(P, MODE)                                                         \
    {                                                                         \
        short2 ff = fp[(P)];                                                  \
        int fo0 = (int)ff.x << 5;                                             \
        float q0 = shB[fo0 + K0];                                             \
        float q1 = shB[fo0 + K1];                                             \
        float q2 = shB[fo0 + K2];                                             \
        float q3 = shB[fo0 + K3];                                             \
        float e1 = shB[((int)ff.y << 5) + lane];                              \
        float w0 = C0*q0*e1, w1 = C1*q1*e1, w2 = C2*q2*e1, w3 = C3*q3*e1;     \
        float x0 = __shfl_sync(FULLMASK, a, S0);                              \
        float x1 = __shfl_sync(FULLMASK, a, S1);                              \
        float x2 = __shfl_sync(FULLMASK, a, S2);                              \
        float x3 = __shfl_sync(FULLMASK, a, S3);                              \
        a = fmaf(x1, w1, x0*w0) + fmaf(x3, w3, x2*w2);                        \
        if ((MODE) == 1) {                                                    \
            int m = __reduce_max_sync(FULLMASK, (__float_as_int(a) >> 23) & 255); \
            sc = __int_as_float((254 - m) << 23);                             \
            pend = m - 127;                                                   \
        }                                                                     \
        if ((MODE) == 2) { a *= sc; expsum += pend; }                         \
    }

    // head: p = 1,2,3
    PAIR(1, 0); PAIR(2, 1); PAIR(3, 2);
    // body: p = 4 .. 1023 in blocks of 4
    for (int pb = 4; pb <= 1020; pb += 4) {
        PAIR(pb+0, 0);
        PAIR(pb+1, 0);
        PAIR(pb+2, 1);
        PAIR(pb+3, 2);
    }
#undef PAIR

    // ---- final: ll = log(sum alpha) + expsum * ln2 ----
    float s = a;
    #pragma unroll
    for (int o = 16; o; o >>= 1) s += __shfl_xor_sync(FULLMASK, s, o);
    if (lane == 0)
        out[row] = logf(s) + 0.6931471805599453f * (float)expsum;
}

// ---------------- entry point ----------------
extern "C" void kernel_launch(void* const* d_in, const int* in_sizes, int n_in,
                              void* d_out, int out_size)
{
    const float* tw     = (const float*)d_in[0];
    const float* ew     = (const float*)d_in[1];
    const float* iw     = (const float*)d_in[2];
    const int*   tokens = (const int*)  d_in[3];
    float*       out    = (float*)d_out;

    int rows = in_sizes[3] / TLEN;

    hmm_fused<<<(rows + 3) / 4, 128>>>(tw, ew, iw, tokens, out, rows);
}

// round 7
// speedup vs baseline: 1.1870x; 1.0429x over previous
#include <cuda_runtime.h>
#include <math.h>

#define FULLMASK 0xffffffffu
#define NS   25
#define NF   216
#define TLEN 2048

// ---------------- constant tables ----------------
__constant__ __align__(16) int c_srcTab[32 * 4] = {
    0,0,0,0,     0,1,1,1,     1,2,2,2,     2,3,3,3,
    3,16,4,4,    4,5,5,5,     5,6,6,6,     6,19,3,7,
    7,8,8,8,     8,9,9,9,     9,22,3,6,    10,11,11,11,
    11,12,12,12, 12,13,13,13, 3,16,14,14,  14,15,15,15,
    15,16,16,16, 6,19,17,17,  17,18,18,18, 18,19,19,19,
    9,22,20,20,  20,21,21,21, 21,22,22,22, 13,23,23,23,
    23,24,24,24, 25,25,25,25, 26,26,26,26, 27,27,27,27,
    28,28,28,28, 29,29,29,29, 30,30,30,30, 31,31,31,31
};
__constant__ int c_deg[32] = {1,1,1,1,2,1,1,3,1,1,4,1,1,2,2,1,1,2,1,1,2,1,1,2,2,0,0,0,0,0,0,0};

__constant__ int c_pred[25][4] = {
    {0,0,0,0},{0,0,0,0},{1,0,0,0},{2,0,0,0},{3,16,0,0},{4,0,0,0},{5,0,0,0},
    {6,19,3,0},{7,0,0,0},{8,0,0,0},{9,22,3,6},{10,0,0,0},{11,0,0,0},{12,13,0,0},
    {3,16,0,0},{14,0,0,0},{15,0,0,0},{6,19,0,0},{17,0,0,0},{18,0,0,0},
    {9,22,0,0},{20,0,0,0},{21,0,0,0},{13,23,0,0},{23,24,0,0}
};
__constant__ int c_pcnt[25] = {1,1,1,1,2,1,1,3,1,1,4,1,1,2,2,1,1,2,1,1,2,1,1,2,2};

__constant__ int c_adds[29][7] = {
    { 0, 10,10,10, 0,1,    0},
    { 1, 10,10, 0, 0,1,   84},
    { 2, 10, 0, 3, 0,1,  105},
    { 3,  0, 3, 2, 0,0,    0},
    { 4,  3, 2,10, 0,1,  111},
    { 5,  2,10,10, 0,1,  123},
    { 6, 10,10,10, 0,1,  159},
    { 7, 10,10,10, 0,1,  243},
    { 8, 10,10,10, 0,1,  327},
    { 9, 10,10,10, 0,1,  411},
    {10, 10,10, 3, 2,1,  495},
    {11, 10, 3, 0, 2,1,  511},
    {11, 10, 3, 2, 2,1,  515},
    {12,  3, 0, 0, 2,0,    0},
    {12,  3, 0, 2, 2,0,    0},
    {12,  3, 2, 0, 2,0,    0},
    {13, 10,10,10, 2,1,  519},
    {14, 10,10,10, 0,1,  583},
    {15, 10,10,10, 0,1,  667},
    {16, 10,10,10, 0,1,  751},
    {17, 10,10,10, 0,1,  835},
    {18, 10,10,10, 0,1,  919},
    {19, 10,10,10, 0,1, 1003},
    {20, 10,10,10, 0,1, 1087},
    {21, 10,10,10, 0,1, 1171},
    {22, 10,10,10, 0,1, 1255},
    {23, 10,10, 5, 2,1, 1339},
    {23, 10, 5, 5, 2,1, 1355},
    {24,  5, 5, 5, 2,0,    0}
};

// ---------------- helpers ----------------
__device__ __forceinline__ int codeList(int ch, int* o) {
    if (ch == 10) { o[0]=0; o[1]=1; o[2]=2; o[3]=3; return 4; }
    o[0] = ch; return 1;
}

__device__ void addB(float* shB, const float* w,
                     int state, int e0, int e1, int e2,
                     int xp, int trainable, int k)
{
    int a0[6], a1[6], a2[6];
    int n0 = codeList(e0, a0);
    int n1 = codeList(e1, a1);
    int n2 = codeList(e2, a2);
    if (xp == 0) { a0[n0++] = 4; a1[n1++] = 4; }
    int t = 0;
    for (int i0 = 0; i0 < n0; i0++) { int c0 = a0[i0];
        for (int i1 = 0; i1 < n1; i1++) { int c1 = a1[i1];
            if (c0 != 4 && c1 == 4) continue;
            for (int i2 = 0; i2 < n2; i2++) { int c2 = a2[i2];
                shB[((c0*36 + c1*6 + c2) << 5) + state] = trainable ? w[k + t] : 1.0f;
                t++;
            }
        }
    }
}

// ---------------- fused kernel ----------------
__global__ __launch_bounds__(128, 1)
void hmm_fused(const float* __restrict__ tw,
               const float* __restrict__ ew,
               const float* __restrict__ iw,
               const int* __restrict__ tokens,
               float* __restrict__ out, int rows)
{
    __shared__ float shB[NF * 32];     // B^T padded: [flat][state(32)]
    __shared__ short sFlat[4 * TLEN];  // per-warp flat contexts
    __shared__ float sA[25 * 25];
    __shared__ float sI[32];
    __shared__ float sRed[4 * 32];
    const int tid = threadIdx.x;

    // ---- init ----
    for (int i = tid; i < NF*32; i += 128) shB[i] = ((i & 31) < 25) ? -1e30f : 0.0f;
    for (int i = tid; i < 25*25;  i += 128) sA[i] = -1e30f;
    __syncthreads();

    // ---- B logits (29 disjoint adds) ----
    if (tid < 29) {
        const int* d = c_adds[tid];
        addB(shB, ew, d[0], d[1], d[2], d[3], d[4], d[5], d[6]);
    }
    // ---- A logits ----
    if (tid == 32) {
        float w0=tw[0],w1=tw[1],w2=tw[2],w3=tw[3],w4=tw[4];
        float w5=tw[5],w6=tw[6],w7=tw[7],w8=tw[8],w9=tw[9];
        sA[0*25+0]=1.f-w0; sA[0*25+1]=w0;
        sA[1*25+2]=1.f;    sA[2*25+3]=1.f;
        sA[3*25+4]=w1;     sA[6*25+7]=w2;
        sA[4*25+5]=1.f;    sA[7*25+8]=1.f;
        sA[5*25+6]=1.f;    sA[8*25+9]=1.f;
        sA[3*25+14]=w3;    sA[6*25+17]=w4;   sA[9*25+20]=w5;
        sA[9*25+10]=1.f-w5;
        sA[14*25+15]=1.f;  sA[17*25+18]=1.f; sA[20*25+21]=1.f;
        sA[15*25+16]=1.f;  sA[18*25+19]=1.f; sA[21*25+22]=1.f;
        sA[16*25+4]=w6;    sA[19*25+7]=w7;   sA[22*25+10]=w8;
        sA[16*25+14]=1.f-w6; sA[19*25+17]=1.f-w7; sA[22*25+20]=1.f-w8;
        sA[3*25+7]=1.f - w9*w9;
        sA[3*25+10]=1.f - w9*w9*w9;
        sA[6*25+10]=1.f - w9*w9;
        sA[10*25+11]=1.f; sA[11*25+12]=1.f; sA[12*25+13]=1.f;
        sA[13*25+13]=1.f; sA[13*25+23]=1.f;
        sA[23*25+23]=1.f; sA[23*25+24]=1.f; sA[24*25+24]=1.f;
    }
    // ---- I softmax (9 entries) ----
    if (tid == 64) {
        float mx = -1e30f;
        for (int i = 0; i < 9; i++) mx = fmaxf(mx, iw[i]);
        float v[9], sum = 0.f;
        for (int i = 0; i < 9; i++) { v[i] = expf(iw[i]-mx); sum += v[i]; }
        for (int i = 0; i < 9; i++) sI[i] = v[i] / sum;
        for (int i = 9; i < 32; i++) sI[i] = 0.f;
    }

    // ---- per-warp: precompute flat contexts for own row ----
    const int lane = tid & 31;
    const int wq   = tid >> 5;
    const int row  = blockIdx.x * 4 + wq;
    short* myFlat = sFlat + wq * TLEN;
    const int* tok = tokens + (size_t)row * TLEN;
    if (row < rows) {
        int c1 = 4, c2 = 4;
        for (int t0 = 0; t0 < TLEN; t0 += 32) {
            int tcv = tok[t0 + lane];
            int t1v = __shfl_up_sync(FULLMASK, tcv, 1);
            int t2v = __shfl_up_sync(FULLMASK, tcv, 2);
            if (lane == 0) { t1v = c1; t2v = c2; }
            if (lane == 1) { t2v = c1; }
            myFlat[t0 + lane] = (short)(t2v*36 + t1v*6 + tcv);
            c2 = __shfl_sync(FULLMASK, tcv, 30);
            c1 = __shfl_sync(FULLMASK, tcv, 31);
        }
    }
    __syncthreads();

    // ---- A row softmax (thread per row) ----
    if (tid < 25) {
        float mx = -1e30f;
        for (int j = 0; j < 25; j++) mx = fmaxf(mx, sA[tid*25+j]);
        float s = 0.f;
        for (int j = 0; j < 25; j++) { float v = expf(sA[tid*25+j]-mx); sA[tid*25+j]=v; s+=v; }
        float inv = 1.f / s;
        for (int j = 0; j < 25; j++) sA[tid*25+j] *= inv;
    }
    // ---- B column softmax, 4-way parallel per state ----
    {
        const int s  = tid & 31;
        const int ch = tid >> 5;
        const int f0 = ch * 54, f1 = f0 + 54;
        float mx = -1e30f;
        for (int f = f0; f < f1; f++) mx = fmaxf(mx, shB[(f<<5)+s]);
        sRed[ch*32 + s] = mx;
        __syncthreads();
        mx = fmaxf(fmaxf(sRed[s], sRed[32+s]), fmaxf(sRed[64+s], sRed[96+s]));
        float sum = 0.f;
        for (int f = f0; f < f1; f++) {
            float v = __expf(shB[(f<<5)+s] - mx);
            shB[(f<<5)+s] = v; sum += v;
        }
        __syncthreads();
        sRed[ch*32 + s] = sum;
        __syncthreads();
        float tot = (sRed[s] + sRed[32+s]) + (sRed[64+s] + sRed[96+s]);
        float inv = 1.f / tot;
        for (int f = f0; f < f1; f++) shB[(f<<5)+s] *= inv;
    }
    __syncthreads();

    // ---- per-lane constants ----
    // 2-step path table; consts folded with 2^15 (exact) to keep alpha centered
    int   ps[4] = {0,0,0,0};
    int   pk[4]; pk[0]=0; pk[1]=0; pk[2]=0; pk[3]=0;
    float pc[4] = {0.f,0.f,0.f,0.f};
    if (lane < 25) {
        int cnt = 0;
        for (int ki = 0; ki < c_pcnt[lane]; ki++) {
            int k = c_pred[lane][ki];
            float akj = sA[k*25 + lane];
            for (int ii = 0; ii < c_pcnt[k]; ii++) {
                int i = c_pred[k][ii];
                ps[cnt] = i; pk[cnt] = k;
                pc[cnt] = sA[i*25 + k] * akj * 32768.0f;   // fold 2^15
                cnt++;
            }
        }
    }
    const int   S0 = ps[0], S1 = ps[1], S2 = ps[2], S3 = ps[3];
    const int   K0 = pk[0], K1 = pk[1], K2 = pk[2], K3 = pk[3];
    const float C0 = pc[0], C1 = pc[1], C2 = pc[2], C3 = pc[3];

    // 1-step table (t=1, unfolded)
    const int u0 = c_srcTab[lane*4+0], u1 = c_srcTab[lane*4+1];
    const int u2 = c_srcTab[lane*4+2], u3 = c_srcTab[lane*4+3];
    const int dg = c_deg[lane];
    float v0 = (lane < 25 && dg > 0) ? sA[u0*25 + lane] : 0.f;
    float v1 = (lane < 25 && dg > 1) ? sA[u1*25 + lane] : 0.f;
    float v2 = (lane < 25 && dg > 2) ? sA[u2*25 + lane] : 0.f;
    float v3 = (lane < 25 && dg > 3) ? sA[u3*25 + lane] : 0.f;

    if (row >= rows) return;

    // ---- t = 0 ----
    float a = sI[lane] * shB[((int)myFlat[0] << 5) + lane];

    // ---- t = 1: single 1-step ----
    {
        float e = shB[((int)myFlat[1] << 5) + lane];
        float x0 = __shfl_sync(FULLMASK, a, u0);
        float x1 = __shfl_sync(FULLMASK, a, u1);
        float x2 = __shfl_sync(FULLMASK, a, u2);
        float x3 = __shfl_sync(FULLMASK, a, u3);
        a = (fmaf(x0, v0, x1*v1) + fmaf(x2, v2, x3*v3)) * e;
    }
    int expsum = 0;
    float sc = 1.f; int pend = 0;

    const short2* fp = (const short2*)myFlat;

#define PAIRM(P, MODE)                                                        \
    {                                                                         \
        short2 ff = fp[(P)];                                                  \
        int fo0 = (int)ff.x << 5;                                             \
        float e1 = shB[((int)ff.y << 5) + lane];                              \
        float w0 = C0 * shB[fo0 + K0] * e1;                                   \
        float w1 = C1 * shB[fo0 + K1] * e1;                                   \
        float w2 = C2 * shB[fo0 + K2] * e1;                                   \
        float w3 = C3 * shB[fo0 + K3] * e1;                                   \
        float x0 = __shfl_sync(FULLMASK, a, S0);                              \
        float x1 = __shfl_sync(FULLMASK, a, S1);                              \
        float x2 = __shfl_sync(FULLMASK, a, S2);                              \
        float x3 = __shfl_sync(FULLMASK, a, S3);                              \
        a = fmaf(x1, w1, x0*w0) + fmaf(x3, w3, x2*w2);                        \
        if ((MODE) == 1) {                                                    \
            int m = __reduce_max_sync(FULLMASK, (__float_as_int(a) >> 23) & 255); \
            sc = __int_as_float((254 - m) << 23);                             \
            pend = m - 127;                                                   \
        }                                                                     \
        if ((MODE) == 2) { a *= sc; expsum += pend; }                         \
    }

    // head: pairs 1..7 (measure at 5, apply at 7)
    PAIRM(1,0) PAIRM(2,0) PAIRM(3,0) PAIRM(4,0) PAIRM(5,1) PAIRM(6,0) PAIRM(7,2)
#undef PAIRM

    // ---- main: 127 blocks of 8 pairs, pairs 8..1023, flats double-buffered ----
    int4 fA = *(const int4*)(myFlat + 16);   // pairs 8..11
    int4 fB = *(const int4*)(myFlat + 24);   // pairs 12..15

#define STAGE(i)                                                              \
    {                                                                         \
        int k_   = cc[(i)];                                                   \
        int fo0_ = (k_ & 0xffff) << 5;                                        \
        int fo1_ = ((int)((unsigned)k_ >> 16)) << 5;                          \
        float e1_ = shB[fo1_ + lane];                                         \
        W[(i)][0] = C0 * shB[fo0_ + K0] * e1_;                                \
        W[(i)][1] = C1 * shB[fo0_ + K1] * e1_;                                \
        W[(i)][2] = C2 * shB[fo0_ + K2] * e1_;                                \
        W[(i)][3] = C3 * shB[fo0_ + K3] * e1_;                                \
    }

    for (int pb = 8; pb <= 1016; pb += 8) {
        int cc[8];
        cc[0]=fA.x; cc[1]=fA.y; cc[2]=fA.z; cc[3]=fA.w;
        cc[4]=fB.x; cc[5]=fB.y; cc[6]=fB.z; cc[7]=fB.w;
        if (pb < 1016) {
            fA = *(const int4*)(myFlat + 2*pb + 16);
            fB = *(const int4*)(myFlat + 2*pb + 24);
        }
        float W[8][4];
        STAGE(0) STAGE(1)
        #pragma unroll
        for (int i = 0; i < 8; i++) {
            if (i < 6) STAGE(i+2)
            float x0 = __shfl_sync(FULLMASK, a, S0);
            float x1 = __shfl_sync(FULLMASK, a, S1);
            float x2 = __shfl_sync(FULLMASK, a, S2);
            float x3 = __shfl_sync(FULLMASK, a, S3);
            a = fmaf(x1, W[i][1], x0*W[i][0]) + fmaf(x3, W[i][3], x2*W[i][2]);
            if (i == 5) {
                int m = __reduce_max_sync(FULLMASK, (__float_as_int(a) >> 23) & 255);
                sc = __int_as_float((254 - m) << 23);
                pend = m - 127;
            }
            if (i == 7) { a *= sc; expsum += pend; }
        }
    }
#undef STAGE

    // ---- final: ll = log(sum alpha) + (expsum - 15*1023) * ln2 ----
    float s = a;
    #pragma unroll
    for (int o = 16; o; o >>= 1) s += __shfl_xor_sync(FULLMASK, s, o);
    if (lane == 0)
        out[row] = logf(s) + 0.6931471805599453f * (float)(expsum - 15345);
}

// ---------------- entry point ----------------
extern "C" void kernel_launch(void* const* d_in, const int* in_sizes, int n_in,
                              void* d_out, int out_size)
{
    const float* tw     = (const float*)d_in[0];
    const float* ew     = (const float*)d_in[1];
    const float* iw     = (const float*)d_in[2];
    const int*   tokens = (const int*)  d_in[3];
    float*       out    = (float*)d_out;

    int rows = in_sizes[3] / TLEN;

    hmm_fused<<<(rows + 3) / 4, 128>>>(tw, ew, iw, tokens, out, rows);
}